// round 1
// baseline (speedup 1.0000x reference)
#include <cuda_runtime.h>

// TokenMixer: out = x_pos * (1 - sigmoid( <x_pre,x_pos> / (||x_pre||*||x_pos||) ))
// Shapes: [N=4096, B=16, C=512] f32. One warp per row (C=512 = 128 float4).
// Each lane: 4 float4 from each input, 3-value warp reduction, scaled store.

#define ROWS_TOTAL (4096 * 16)
#define F4_PER_ROW 128   // 512 floats / 4
#define WARPS_PER_BLOCK 8

__global__ __launch_bounds__(WARPS_PER_BLOCK * 32)
void token_mixer_kernel(const float4* __restrict__ pre,
                        const float4* __restrict__ pos,
                        float4* __restrict__ out) {
    const int warp_id = threadIdx.x >> 5;
    const int lane    = threadIdx.x & 31;
    const int row     = blockIdx.x * WARPS_PER_BLOCK + warp_id;
    if (row >= ROWS_TOTAL) return;

    const size_t base = (size_t)row * F4_PER_ROW;
    const float4* __restrict__ p = pre + base;
    const float4* __restrict__ q = pos + base;

    float4 b0, b1, b2, b3;
    float dot = 0.f, sa = 0.f, sb = 0.f;

    // Load both rows (coalesced: lane + 32*i), accumulate partials.
    {
        float4 a;
        a = p[lane +  0]; b0 = q[lane +  0];
        dot += a.x*b0.x + a.y*b0.y + a.z*b0.z + a.w*b0.w;
        sa  += a.x*a.x  + a.y*a.y  + a.z*a.z  + a.w*a.w;
        sb  += b0.x*b0.x + b0.y*b0.y + b0.z*b0.z + b0.w*b0.w;

        a = p[lane + 32]; b1 = q[lane + 32];
        dot += a.x*b1.x + a.y*b1.y + a.z*b1.z + a.w*b1.w;
        sa  += a.x*a.x  + a.y*a.y  + a.z*a.z  + a.w*a.w;
        sb  += b1.x*b1.x + b1.y*b1.y + b1.z*b1.z + b1.w*b1.w;

        a = p[lane + 64]; b2 = q[lane + 64];
        dot += a.x*b2.x + a.y*b2.y + a.z*b2.z + a.w*b2.w;
        sa  += a.x*a.x  + a.y*a.y  + a.z*a.z  + a.w*a.w;
        sb  += b2.x*b2.x + b2.y*b2.y + b2.z*b2.z + b2.w*b2.w;

        a = p[lane + 96]; b3 = q[lane + 96];
        dot += a.x*b3.x + a.y*b3.y + a.z*b3.z + a.w*b3.w;
        sa  += a.x*a.x  + a.y*a.y  + a.z*a.z  + a.w*a.w;
        sb  += b3.x*b3.x + b3.y*b3.y + b3.z*b3.z + b3.w*b3.w;
    }

    // Warp tree-reduce the three scalars.
    #pragma unroll
    for (int off = 16; off > 0; off >>= 1) {
        dot += __shfl_xor_sync(0xffffffffu, dot, off);
        sa  += __shfl_xor_sync(0xffffffffu, sa,  off);
        sb  += __shfl_xor_sync(0xffffffffu, sb,  off);
    }

    const float na = fmaxf(sqrtf(sa), 1e-12f);
    const float nb = fmaxf(sqrtf(sb), 1e-12f);
    const float d  = dot / (na * nb);
    // 1 - sigmoid(d) = 1 / (1 + exp(d))
    const float w  = 1.0f / (1.0f + __expf(d));

    float4* __restrict__ o = out + base;
    b0.x *= w; b0.y *= w; b0.z *= w; b0.w *= w;
    b1.x *= w; b1.y *= w; b1.z *= w; b1.w *= w;
    b2.x *= w; b2.y *= w; b2.z *= w; b2.w *= w;
    b3.x *= w; b3.y *= w; b3.z *= w; b3.w *= w;
    o[lane +  0] = b0;
    o[lane + 32] = b1;
    o[lane + 64] = b2;
    o[lane + 96] = b3;
}

extern "C" void kernel_launch(void* const* d_in, const int* in_sizes, int n_in,
                              void* d_out, int out_size) {
    const float4* pre = (const float4*)d_in[0];
    const float4* pos = (const float4*)d_in[1];
    float4* out = (float4*)d_out;
    const int blocks = ROWS_TOTAL / WARPS_PER_BLOCK;  // 8192
    token_mixer_kernel<<<blocks, WARPS_PER_BLOCK * 32>>>(pre, pos, out);
}

// round 2
// speedup vs baseline: 1.0133x; 1.0133x over previous
#include <cuda_runtime.h>

// TokenMixer: out = x_pos * (1 - sigmoid( <x_pre,x_pos> / (||x_pre||*||x_pos||) ))
// Shapes: [N=4096, B=16, C=512] f32. One warp per row (C=512 = 128 float4).
// R2: streaming cache hints (__ldcs / __stcs) — all traffic is single-use,
// so mark every access evict-first to keep L2 from churning useful sectors.

#define ROWS_TOTAL (4096 * 16)
#define F4_PER_ROW 128   // 512 floats / 4
#define WARPS_PER_BLOCK 8

__global__ __launch_bounds__(WARPS_PER_BLOCK * 32)
void token_mixer_kernel(const float4* __restrict__ pre,
                        const float4* __restrict__ pos,
                        float4* __restrict__ out) {
    const int warp_id = threadIdx.x >> 5;
    const int lane    = threadIdx.x & 31;
    const int row     = blockIdx.x * WARPS_PER_BLOCK + warp_id;  // exact: 8192*8 == ROWS_TOTAL

    const size_t base = (size_t)row * F4_PER_ROW;
    const float4* __restrict__ p = pre + base + lane;
    const float4* __restrict__ q = pos + base + lane;

    // Front-batch all 8 loads (MLP_p1 = 8) with streaming hints.
    float4 a0 = __ldcs(p +  0);
    float4 b0 = __ldcs(q +  0);
    float4 a1 = __ldcs(p + 32);
    float4 b1 = __ldcs(q + 32);
    float4 a2 = __ldcs(p + 64);
    float4 b2 = __ldcs(q + 64);
    float4 a3 = __ldcs(p + 96);
    float4 b3 = __ldcs(q + 96);

    float dot = 0.f, sa = 0.f, sb = 0.f;
    dot += a0.x*b0.x + a0.y*b0.y + a0.z*b0.z + a0.w*b0.w;
    sa  += a0.x*a0.x + a0.y*a0.y + a0.z*a0.z + a0.w*a0.w;
    sb  += b0.x*b0.x + b0.y*b0.y + b0.z*b0.z + b0.w*b0.w;

    dot += a1.x*b1.x + a1.y*b1.y + a1.z*b1.z + a1.w*b1.w;
    sa  += a1.x*a1.x + a1.y*a1.y + a1.z*a1.z + a1.w*a1.w;
    sb  += b1.x*b1.x + b1.y*b1.y + b1.z*b1.z + b1.w*b1.w;

    dot += a2.x*b2.x + a2.y*b2.y + a2.z*b2.z + a2.w*b2.w;
    sa  += a2.x*a2.x + a2.y*a2.y + a2.z*a2.z + a2.w*a2.w;
    sb  += b2.x*b2.x + b2.y*b2.y + b2.z*b2.z + b2.w*b2.w;

    dot += a3.x*b3.x + a3.y*b3.y + a3.z*b3.z + a3.w*b3.w;
    sa  += a3.x*a3.x + a3.y*a3.y + a3.z*a3.z + a3.w*a3.w;
    sb  += b3.x*b3.x + b3.y*b3.y + b3.z*b3.z + b3.w*b3.w;

    // Warp tree-reduce the three scalars.
    #pragma unroll
    for (int off = 16; off > 0; off >>= 1) {
        dot += __shfl_xor_sync(0xffffffffu, dot, off);
        sa  += __shfl_xor_sync(0xffffffffu, sa,  off);
        sb  += __shfl_xor_sync(0xffffffffu, sb,  off);
    }

    const float na = fmaxf(sqrtf(sa), 1e-12f);
    const float nb = fmaxf(sqrtf(sb), 1e-12f);
    const float d  = dot / (na * nb);
    // 1 - sigmoid(d) = 1 / (1 + exp(d))
    const float w  = 1.0f / (1.0f + __expf(d));

    float4* __restrict__ o = out + base + lane;
    b0.x *= w; b0.y *= w; b0.z *= w; b0.w *= w;
    b1.x *= w; b1.y *= w; b1.z *= w; b1.w *= w;
    b2.x *= w; b2.y *= w; b2.z *= w; b2.w *= w;
    b3.x *= w; b3.y *= w; b3.z *= w; b3.w *= w;
    __stcs(o +  0, b0);
    __stcs(o + 32, b1);
    __stcs(o + 64, b2);
    __stcs(o + 96, b3);
}

extern "C" void kernel_launch(void* const* d_in, const int* in_sizes, int n_in,
                              void* d_out, int out_size) {
    const float4* pre = (const float4*)d_in[0];
    const float4* pos = (const float4*)d_in[1];
    float4* out = (float4*)d_out;
    const int blocks = ROWS_TOTAL / WARPS_PER_BLOCK;  // 8192
    token_mixer_kernel<<<blocks, WARPS_PER_BLOCK * 32>>>(pre, pos, out);
}

// round 3
// speedup vs baseline: 1.0190x; 1.0057x over previous
#include <cuda_runtime.h>

// TokenMixer: out = x_pos * (1 - sigmoid( <x_pre,x_pos> / (||x_pre||*||x_pos||) ))
// Shapes: [N=4096, B=16, C=512] f32.
// R3: 2 rows per warp. Each warp streams 4KB contiguous from each input
// (16 front-batched float4 loads/lane -> MLP=16), two independent reduce
// chains pipeline together, one tail amortized over 2 rows. Plain loads
// (R2 showed .cs hints regress DRAM efficiency on sm_103a).

#define ROWS_TOTAL (4096 * 16)
#define F4_PER_ROW 128          // 512 floats / 4
#define WARPS_PER_BLOCK 8
#define ROWS_PER_WARP 2
#define ROWS_PER_BLOCK (WARPS_PER_BLOCK * ROWS_PER_WARP)   // 16

__global__ __launch_bounds__(WARPS_PER_BLOCK * 32)
void token_mixer_kernel(const float4* __restrict__ pre,
                        const float4* __restrict__ pos,
                        float4* __restrict__ out) {
    const int warp_id = threadIdx.x >> 5;
    const int lane    = threadIdx.x & 31;
    // Warp handles rows [2w, 2w+1] -> a contiguous 256-float4 span.
    const int row0 = (blockIdx.x * WARPS_PER_BLOCK + warp_id) * ROWS_PER_WARP;

    const size_t base = (size_t)row0 * F4_PER_ROW;
    const float4* __restrict__ p = pre + base + lane;
    const float4* __restrict__ q = pos + base + lane;

    // Front-batch all 16 loads. Chunks 0-3 belong to row0, 4-7 to row1.
    float4 a0 = p[  0]; float4 b0 = q[  0];
    float4 a1 = p[ 32]; float4 b1 = q[ 32];
    float4 a2 = p[ 64]; float4 b2 = q[ 64];
    float4 a3 = p[ 96]; float4 b3 = q[ 96];
    float4 a4 = p[128]; float4 b4 = q[128];
    float4 a5 = p[160]; float4 b5 = q[160];
    float4 a6 = p[192]; float4 b6 = q[192];
    float4 a7 = p[224]; float4 b7 = q[224];

    float d0 = 0.f, sa0 = 0.f, sb0 = 0.f;   // row0 accumulators
    float d1 = 0.f, sa1 = 0.f, sb1 = 0.f;   // row1 accumulators

    d0  += a0.x*b0.x + a0.y*b0.y + a0.z*b0.z + a0.w*b0.w;
    sa0 += a0.x*a0.x + a0.y*a0.y + a0.z*a0.z + a0.w*a0.w;
    sb0 += b0.x*b0.x + b0.y*b0.y + b0.z*b0.z + b0.w*b0.w;

    d0  += a1.x*b1.x + a1.y*b1.y + a1.z*b1.z + a1.w*b1.w;
    sa0 += a1.x*a1.x + a1.y*a1.y + a1.z*a1.z + a1.w*a1.w;
    sb0 += b1.x*b1.x + b1.y*b1.y + b1.z*b1.z + b1.w*b1.w;

    d0  += a2.x*b2.x + a2.y*b2.y + a2.z*b2.z + a2.w*b2.w;
    sa0 += a2.x*a2.x + a2.y*a2.y + a2.z*a2.z + a2.w*a2.w;
    sb0 += b2.x*b2.x + b2.y*b2.y + b2.z*b2.z + b2.w*b2.w;

    d0  += a3.x*b3.x + a3.y*b3.y + a3.z*b3.z + a3.w*b3.w;
    sa0 += a3.x*a3.x + a3.y*a3.y + a3.z*a3.z + a3.w*a3.w;
    sb0 += b3.x*b3.x + b3.y*b3.y + b3.z*b3.z + b3.w*b3.w;

    d1  += a4.x*b4.x + a4.y*b4.y + a4.z*b4.z + a4.w*b4.w;
    sa1 += a4.x*a4.x + a4.y*a4.y + a4.z*a4.z + a4.w*a4.w;
    sb1 += b4.x*b4.x + b4.y*b4.y + b4.z*b4.z + b4.w*b4.w;

    d1  += a5.x*b5.x + a5.y*b5.y + a5.z*b5.z + a5.w*b5.w;
    sa1 += a5.x*a5.x + a5.y*a5.y + a5.z*a5.z + a5.w*a5.w;
    sb1 += b5.x*b5.x + b5.y*b5.y + b5.z*b5.z + b5.w*b5.w;

    d1  += a6.x*b6.x + a6.y*b6.y + a6.z*b6.z + a6.w*b6.w;
    sa1 += a6.x*a6.x + a6.y*a6.y + a6.z*a6.z + a6.w*a6.w;
    sb1 += b6.x*b6.x + b6.y*b6.y + b6.z*b6.z + b6.w*b6.w;

    d1  += a7.x*b7.x + a7.y*b7.y + a7.z*b7.z + a7.w*b7.w;
    sa1 += a7.x*a7.x + a7.y*a7.y + a7.z*a7.z + a7.w*a7.w;
    sb1 += b7.x*b7.x + b7.y*b7.y + b7.z*b7.z + b7.w*b7.w;

    // Two independent 3-value warp reductions (pipeline through SHFL unit).
    #pragma unroll
    for (int off = 16; off > 0; off >>= 1) {
        d0  += __shfl_xor_sync(0xffffffffu, d0,  off);
        d1  += __shfl_xor_sync(0xffffffffu, d1,  off);
        sa0 += __shfl_xor_sync(0xffffffffu, sa0, off);
        sa1 += __shfl_xor_sync(0xffffffffu, sa1, off);
        sb0 += __shfl_xor_sync(0xffffffffu, sb0, off);
        sb1 += __shfl_xor_sync(0xffffffffu, sb1, off);
    }

    const float na0 = fmaxf(sqrtf(sa0), 1e-12f);
    const float nb0 = fmaxf(sqrtf(sb0), 1e-12f);
    const float na1 = fmaxf(sqrtf(sa1), 1e-12f);
    const float nb1 = fmaxf(sqrtf(sb1), 1e-12f);
    const float c0 = d0 / (na0 * nb0);
    const float c1 = d1 / (na1 * nb1);
    // 1 - sigmoid(c) = 1 / (1 + exp(c))
    const float w0 = 1.0f / (1.0f + __expf(c0));
    const float w1 = 1.0f / (1.0f + __expf(c1));

    float4* __restrict__ o = out + base + lane;
    b0.x *= w0; b0.y *= w0; b0.z *= w0; b0.w *= w0;
    b1.x *= w0; b1.y *= w0; b1.z *= w0; b1.w *= w0;
    b2.x *= w0; b2.y *= w0; b2.z *= w0; b2.w *= w0;
    b3.x *= w0; b3.y *= w0; b3.z *= w0; b3.w *= w0;
    b4.x *= w1; b4.y *= w1; b4.z *= w1; b4.w *= w1;
    b5.x *= w1; b5.y *= w1; b5.z *= w1; b5.w *= w1;
    b6.x *= w1; b6.y *= w1; b6.z *= w1; b6.w *= w1;
    b7.x *= w1; b7.y *= w1; b7.z *= w1; b7.w *= w1;
    o[  0] = b0;
    o[ 32] = b1;
    o[ 64] = b2;
    o[ 96] = b3;
    o[128] = b4;
    o[160] = b5;
    o[192] = b6;
    o[224] = b7;
}

extern "C" void kernel_launch(void* const* d_in, const int* in_sizes, int n_in,
                              void* d_out, int out_size) {
    const float4* pre = (const float4*)d_in[0];
    const float4* pos = (const float4*)d_in[1];
    float4* out = (float4*)d_out;
    const int blocks = ROWS_TOTAL / ROWS_PER_BLOCK;  // 4096
    token_mixer_kernel<<<blocks, WARPS_PER_BLOCK * 32>>>(pre, pos, out);
}